// round 3
// baseline (speedup 1.0000x reference)
#include <cuda_runtime.h>
#include <cuda_bf16.h>

typedef unsigned long long u64;

#define T_LEN  128
#define H3     60
#define HID    20
#define LOUT   15
#define NB     2048
#define VOCAB  256

// preprocessed embedding table: W0b = W0 + b0i (broadcast over rows)
__device__ float W0b_buf[VOCAB * H3];

__global__ void prep_kernel(const float* __restrict__ W0, const float* __restrict__ b0i){
  int i = blockIdx.x * blockDim.x + threadIdx.x;
  if (i < VOCAB * H3) W0b_buf[i] = W0[i] + b0i[i % H3];
}

__device__ __forceinline__ u64 fma2(u64 a, u64 b, u64 c){
  u64 d; asm("fma.rn.f32x2 %0, %1, %2, %3;" : "=l"(d) : "l"(a), "l"(b), "l"(c)); return d;
}
__device__ __forceinline__ u64 add2(u64 a, u64 b){
  u64 d; asm("add.rn.f32x2 %0, %1, %2;" : "=l"(d) : "l"(a), "l"(b)); return d;
}
__device__ __forceinline__ u64 pack2(float x, float y){
  u64 d; asm("mov.b64 %0, {%1, %2};" : "=l"(d) : "f"(x), "f"(y)); return d;
}
__device__ __forceinline__ float tanh_ap(float x){
  float y; asm("tanh.approx.f32 %0, %1;" : "=f"(y) : "f"(x)); return y;
}
__device__ __forceinline__ float sig_ap(float x){
  return fmaf(0.5f, tanh_ap(0.5f * x), 0.5f);
}

__global__ void __launch_bounds__(32, 14) gru2_kernel(
    const int*   __restrict__ x,
    const float* __restrict__ U0,  const float* __restrict__ b0r,
    const float* __restrict__ W1,  const float* __restrict__ U1,
    const float* __restrict__ b1i, const float* __restrict__ b1r,
    const float* __restrict__ Wd,  const float* __restrict__ bd,
    float* __restrict__ out)
{
  const int t  = threadIdx.x;
  const int b  = blockIdx.x;
  const int jc = (t < 30) ? 2 * t : 0;     // column pair owned by this lane

  // hidden states DUPLICATED: hd[2k]=hd[2k+1]=h_k  -> LDS.128 = two {h,h} f32x2 operands
  __shared__ __align__(16) float hd0[40];
  __shared__ __align__(16) float hd1[40];
  __shared__ __align__(8)  float sA[64];   // cols 0..39: z|r combined preact; 40..59: xh part
  __shared__ __align__(8)  float sR[64];   // cols 40..59: rh part
  __shared__ int xs[T_LEN];

  // ---- resident weights: packed f32x2 column pairs ----
  u64 u0w[HID], w1w[HID], u1w[HID];
#pragma unroll
  for (int k = 0; k < HID; k++){
    u0w[k] = *(const u64*)(U0 + k * H3 + jc);
    w1w[k] = *(const u64*)(W1 + k * H3 + jc);
    u1w[k] = *(const u64*)(U1 + k * H3 + jc);
  }
  const u64 b0rp = *(const u64*)(b0r + jc);
  const u64 b1ip = *(const u64*)(b1i + jc);
  const u64 b1rp = *(const u64*)(b1r + jc);

#pragma unroll
  for (int i = t; i < 40; i += 32){ hd0[i] = 0.f; hd1[i] = 0.f; }
#pragma unroll 4
  for (int i = t; i < T_LEN; i += 32) xs[i] = x[(long)b * T_LEN + i];
  __syncwarp();

  float hp0 = 0.f, hp1 = 0.f;       // lane t<20 keeps h_t of layer0/1

  u64 gx = *(const u64*)(W0b_buf + xs[0] * H3 + jc);   // xW0+b0i for step 0

  const ulonglong2* h0v = (const ulonglong2*)hd0;
  const ulonglong2* h1v = (const ulonglong2*)hd1;

  for (int step = 0; step < T_LEN; step++){
    // prefetch next step's embedding gather (L1/L2 resident table)
    const int nt = (step + 1 < T_LEN) ? step + 1 : step;
    const u64 ngx = *(const u64*)(W0b_buf + xs[nt] * H3 + jc);

    // ===== layer 0: rec = h0 @ U0 + b0r ; combine with xw =====
    {
      u64 ra = b0rp, rb = 0ull;
#pragma unroll
      for (int i = 0; i < 10; i++){
        const ulonglong2 hv = h0v[i];
        ra = fma2(u0w[2*i],     hv.x, ra);
        rb = fma2(u0w[2*i + 1], hv.y, rb);
      }
      const u64 rec = add2(ra, rb);
      if (t < 20){
        *(u64*)&sA[jc] = add2(gx, rec);      // z,r: combined directly
      } else if (t < 30){
        *(u64*)&sA[jc] = gx;                 // xh
        *(u64*)&sR[jc] = rec;                // rh
      }
    }
    __syncwarp();

    if (t < HID){
      const float z  = sig_ap(sA[t]);
      const float r  = sig_ap(sA[20 + t]);
      const float hh = tanh_ap(fmaf(r, sR[40 + t], sA[40 + t]));
      const float hn = fmaf(z, hp0 - hh, hh);          // z*h + (1-z)*hh
      hp0 = hn;
      *(u64*)&hd0[2*t] = pack2(hn, hn);
    }
    __syncwarp();

    // ===== layer 1: xw1 = h0 @ W1 + b1i ; rec1 = h1 @ U1 + b1r =====
    {
      u64 aa = b1ip, ab = 0ull;
      u64 ra = b1rp, rb = 0ull;
#pragma unroll
      for (int i = 0; i < 10; i++){
        const ulonglong2 hv0 = h0v[i];
        const ulonglong2 hv1 = h1v[i];
        aa = fma2(w1w[2*i],     hv0.x, aa);
        ab = fma2(w1w[2*i + 1], hv0.y, ab);
        ra = fma2(u1w[2*i],     hv1.x, ra);
        rb = fma2(u1w[2*i + 1], hv1.y, rb);
      }
      const u64 acc = add2(aa, ab);
      const u64 rec = add2(ra, rb);
      if (t < 20){
        *(u64*)&sA[jc] = add2(acc, rec);
      } else if (t < 30){
        *(u64*)&sA[jc] = acc;
        *(u64*)&sR[jc] = rec;
      }
    }
    __syncwarp();

    if (t < HID){
      const float z  = sig_ap(sA[t]);
      const float r  = sig_ap(sA[20 + t]);
      const float hh = tanh_ap(fmaf(r, sR[40 + t], sA[40 + t]));
      const float hn = fmaf(z, hp1 - hh, hh);
      hp1 = hn;
      *(u64*)&hd1[2*t] = pack2(hn, hn);
    }
    __syncwarp();

    gx = ngx;
  }

  // ===== epilogue: softmax(h1 @ Wd + bd) =====
  float val = -1e30f;
  if (t < LOUT){
    float acc = bd[t];
#pragma unroll
    for (int k = 0; k < HID; k++)
      acc = fmaf(hd1[2*k], Wd[k * LOUT + t], acc);
    val = acc;
  }
  float m = val;
#pragma unroll
  for (int off = 16; off > 0; off >>= 1)
    m = fmaxf(m, __shfl_xor_sync(0xffffffffu, m, off));
  const float e = (t < LOUT) ? __expf(val - m) : 0.f;
  float s = e;
#pragma unroll
  for (int off = 16; off > 0; off >>= 1)
    s += __shfl_xor_sync(0xffffffffu, s, off);
  if (t < LOUT)
    out[(long)b * LOUT + t] = __fdividef(e, s);
}

extern "C" void kernel_launch(void* const* d_in, const int* in_sizes, int n_in,
                              void* d_out, int out_size)
{
  const int*   x   = (const int*)  d_in[0];
  const float* W0  = (const float*)d_in[1];
  const float* U0  = (const float*)d_in[2];
  const float* b0i = (const float*)d_in[3];
  const float* b0r = (const float*)d_in[4];
  const float* W1  = (const float*)d_in[5];
  const float* U1  = (const float*)d_in[6];
  const float* b1i = (const float*)d_in[7];
  const float* b1r = (const float*)d_in[8];
  const float* Wd  = (const float*)d_in[9];
  const float* bd  = (const float*)d_in[10];
  // d_in[11] = drop_rate (identity, ignored)
  float* out = (float*)d_out;

  prep_kernel<<<(VOCAB * H3 + 255) / 256, 256>>>(W0, b0i);
  gru2_kernel<<<NB, 32>>>(x, U0, b0r, W1, U1, b1i, b1r, Wd, bd, out);
}

// round 4
// speedup vs baseline: 1.7945x; 1.7945x over previous
#include <cuda_runtime.h>
#include <cuda_bf16.h>

typedef unsigned long long u64;

#define T_LEN  128
#define H3     60
#define HID    20
#define LOUT   15
#define NB     2048

__device__ __forceinline__ u64 fma2(u64 a, u64 b, u64 c){
  u64 d; asm("fma.rn.f32x2 %0, %1, %2, %3;" : "=l"(d) : "l"(a), "l"(b), "l"(c)); return d;
}
__device__ __forceinline__ u64 add2(u64 a, u64 b){
  u64 d; asm("add.rn.f32x2 %0, %1, %2;" : "=l"(d) : "l"(a), "l"(b)); return d;
}
__device__ __forceinline__ u64 pack2(float x, float y){
  u64 d; asm("mov.b64 %0, {%1, %2};" : "=l"(d) : "f"(x), "f"(y)); return d;
}
__device__ __forceinline__ float tanh_ap(float x){
  float y; asm("tanh.approx.f32 %0, %1;" : "=f"(y) : "f"(x)); return y;
}
__device__ __forceinline__ float sig_ap(float x){
  return fmaf(0.5f, tanh_ap(0.5f * x), 0.5f);
}

__global__ void __launch_bounds__(32) gru2_kernel(
    const int*   __restrict__ x,
    const float* __restrict__ W0,
    const float* __restrict__ U0,  const float* __restrict__ b0i, const float* __restrict__ b0r,
    const float* __restrict__ W1,  const float* __restrict__ U1,
    const float* __restrict__ b1i, const float* __restrict__ b1r,
    const float* __restrict__ Wd,  const float* __restrict__ bd,
    float* __restrict__ out)
{
  const int t     = threadIdx.x;
  const int bbase = blockIdx.x * 2;
  const int jc    = (t < 30) ? 2 * t : 0;   // column pair owned by this lane

  // hidden states DUPLICATED: hd[be][2k]=hd[be][2k+1]=h_k -> LDS.128 = two {h,h} f32x2 operands
  __shared__ __align__(16) float hd0[2][40];
  __shared__ __align__(16) float hd1[2][40];
  __shared__ __align__(8)  float sAcc[2][72];  // input-path preactivation (cols 0..59)
  __shared__ __align__(8)  float sRec[2][72];  // recurrent-path preactivation
  __shared__ int xs[2][T_LEN];

  // ---- resident weights: packed f32x2 column pairs (120 regs) ----
  u64 u0w[HID], w1w[HID], u1w[HID];
#pragma unroll
  for (int k = 0; k < HID; k++){
    u0w[k] = *(const u64*)(U0 + k * H3 + jc);
    w1w[k] = *(const u64*)(W1 + k * H3 + jc);
    u1w[k] = *(const u64*)(U1 + k * H3 + jc);
  }
  const u64 b0ip = *(const u64*)(b0i + jc);
  const u64 b0rp = *(const u64*)(b0r + jc);
  const u64 b1ip = *(const u64*)(b1i + jc);
  const u64 b1rp = *(const u64*)(b1r + jc);

#pragma unroll
  for (int i = t; i < 40; i += 32){
    hd0[0][i] = 0.f; hd0[1][i] = 0.f;
    hd1[0][i] = 0.f; hd1[1][i] = 0.f;
  }
#pragma unroll 4
  for (int i = t; i < T_LEN; i += 32){
    xs[0][i] = x[(long)bbase * T_LEN + i];
    xs[1][i] = x[(long)(bbase + 1) * T_LEN + i];
  }
  __syncwarp();

  float hp0[2] = {0.f, 0.f};   // lane t keeps h_t (meaningful for t<20)
  float hp1[2] = {0.f, 0.f};

  u64 gx[2];
  gx[0] = *(const u64*)(W0 + xs[0][0] * H3 + jc);
  gx[1] = *(const u64*)(W0 + xs[1][0] * H3 + jc);

  const ulonglong2* h0v0 = (const ulonglong2*)hd0[0];
  const ulonglong2* h0v1 = (const ulonglong2*)hd0[1];
  const ulonglong2* h1v0 = (const ulonglong2*)hd1[0];
  const ulonglong2* h1v1 = (const ulonglong2*)hd1[1];

  for (int step = 0; step < T_LEN; step++){
    // prefetch next step's W0 gather (L1/L2-resident 61 KB table)
    const int nt = (step + 1 < T_LEN) ? step + 1 : step;
    const u64 ngx0 = *(const u64*)(W0 + xs[0][nt] * H3 + jc);
    const u64 ngx1 = *(const u64*)(W0 + xs[1][nt] * H3 + jc);

    // ===== layer 0 matvec: rec = h0 @ U0 + b0r ; acc = xW0 + b0i =====
#pragma unroll
    for (int be = 0; be < 2; be++){
      const ulonglong2* hv = be ? h0v1 : h0v0;
      u64 ra = b0rp, rb = 0ull;
#pragma unroll
      for (int i = 0; i < 10; i++){
        const ulonglong2 h2 = hv[i];
        ra = fma2(u0w[2*i],     h2.x, ra);
        rb = fma2(u0w[2*i + 1], h2.y, rb);
      }
      if (t < 30){
        *(u64*)&sAcc[be][jc] = add2(gx[be], b0ip);
        *(u64*)&sRec[be][jc] = add2(ra, rb);
      }
    }
    __syncwarp();

    // ===== layer 0 nonlinearity (all lanes; only t<20 results used) =====
#pragma unroll
    for (int be = 0; be < 2; be++){
      const float z  = sig_ap(sAcc[be][t]      + sRec[be][t]);
      const float r  = sig_ap(sAcc[be][20 + t] + sRec[be][20 + t]);
      const float hh = tanh_ap(fmaf(r, sRec[be][40 + t], sAcc[be][40 + t]));
      const float hn = fmaf(z, hp0[be] - hh, hh);       // z*h + (1-z)*hh
      hp0[be] = hn;
      if (t < HID) *(u64*)&hd0[be][2*t] = pack2(hn, hn);
    }
    __syncwarp();

    // ===== layer 1 matvec: acc = h0 @ W1 + b1i ; rec = h1 @ U1 + b1r =====
#pragma unroll
    for (int be = 0; be < 2; be++){
      const ulonglong2* hv0 = be ? h0v1 : h0v0;
      const ulonglong2* hv1 = be ? h1v1 : h1v0;
      u64 aa = b1ip, ab = 0ull;
      u64 ra = b1rp, rb = 0ull;
#pragma unroll
      for (int i = 0; i < 10; i++){
        const ulonglong2 a2 = hv0[i];
        const ulonglong2 r2 = hv1[i];
        aa = fma2(w1w[2*i],     a2.x, aa);
        ab = fma2(w1w[2*i + 1], a2.y, ab);
        ra = fma2(u1w[2*i],     r2.x, ra);
        rb = fma2(u1w[2*i + 1], r2.y, rb);
      }
      if (t < 30){
        *(u64*)&sAcc[be][jc] = add2(aa, ab);
        *(u64*)&sRec[be][jc] = add2(ra, rb);
      }
    }
    __syncwarp();

    // ===== layer 1 nonlinearity =====
#pragma unroll
    for (int be = 0; be < 2; be++){
      const float z  = sig_ap(sAcc[be][t]      + sRec[be][t]);
      const float r  = sig_ap(sAcc[be][20 + t] + sRec[be][20 + t]);
      const float hh = tanh_ap(fmaf(r, sRec[be][40 + t], sAcc[be][40 + t]));
      const float hn = fmaf(z, hp1[be] - hh, hh);
      hp1[be] = hn;
      if (t < HID) *(u64*)&hd1[be][2*t] = pack2(hn, hn);
    }
    __syncwarp();

    gx[0] = ngx0;
    gx[1] = ngx1;
  }

  // ===== epilogue: softmax(h1 @ Wd + bd) =====
#pragma unroll
  for (int be = 0; be < 2; be++){
    float val = -1e30f;
    if (t < LOUT){
      float acc = bd[t];
#pragma unroll
      for (int k = 0; k < HID; k++)
        acc = fmaf(hd1[be][2*k], Wd[k * LOUT + t], acc);
      val = acc;
    }
    float m = val;
#pragma unroll
    for (int off = 16; off > 0; off >>= 1)
      m = fmaxf(m, __shfl_xor_sync(0xffffffffu, m, off));
    const float e = (t < LOUT) ? __expf(val - m) : 0.f;
    float s = e;
#pragma unroll
    for (int off = 16; off > 0; off >>= 1)
      s += __shfl_xor_sync(0xffffffffu, s, off);
    if (t < LOUT)
      out[(long)(bbase + be) * LOUT + t] = __fdividef(e, s);
  }
}

extern "C" void kernel_launch(void* const* d_in, const int* in_sizes, int n_in,
                              void* d_out, int out_size)
{
  const int*   x   = (const int*)  d_in[0];
  const float* W0  = (const float*)d_in[1];
  const float* U0  = (const float*)d_in[2];
  const float* b0i = (const float*)d_in[3];
  const float* b0r = (const float*)d_in[4];
  const float* W1  = (const float*)d_in[5];
  const float* U1  = (const float*)d_in[6];
  const float* b1i = (const float*)d_in[7];
  const float* b1r = (const float*)d_in[8];
  const float* Wd  = (const float*)d_in[9];
  const float* bd  = (const float*)d_in[10];
  // d_in[11] = drop_rate (identity, ignored)
  float* out = (float*)d_out;

  gru2_kernel<<<NB / 2, 32>>>(x, W0, U0, b0i, b0r, W1, U1, b1i, b1r, Wd, bd, out);
}

// round 7
// speedup vs baseline: 1.7993x; 1.0027x over previous
#include <cuda_runtime.h>
#include <cuda_bf16.h>

typedef unsigned long long u64;

#define T_LEN  128
#define H3     60
#define HID    20
#define LOUT   15
#define NB     2048

__device__ __forceinline__ u64 fma2(u64 a, u64 b, u64 c){
  u64 d; asm("fma.rn.f32x2 %0, %1, %2, %3;" : "=l"(d) : "l"(a), "l"(b), "l"(c)); return d;
}
__device__ __forceinline__ u64 add2(u64 a, u64 b){
  u64 d; asm("add.rn.f32x2 %0, %1, %2;" : "=l"(d) : "l"(a), "l"(b)); return d;
}
__device__ __forceinline__ u64 pack2(float x, float y){
  u64 d; asm("mov.b64 %0, {%1, %2};" : "=l"(d) : "f"(x), "f"(y)); return d;
}
__device__ __forceinline__ float tanh_ap(float x){
  float y; asm("tanh.approx.f32 %0, %1;" : "=f"(y) : "f"(x)); return y;
}
__device__ __forceinline__ float sig_ap(float x){
  return fmaf(0.5f, tanh_ap(0.5f * x), 0.5f);
}

__global__ void __launch_bounds__(64) gru2_kernel(
    const int*   __restrict__ x,
    const float* __restrict__ W0,
    const float* __restrict__ U0,  const float* __restrict__ b0i, const float* __restrict__ b0r,
    const float* __restrict__ W1,  const float* __restrict__ U1,
    const float* __restrict__ b1i, const float* __restrict__ b1r,
    const float* __restrict__ Wd,  const float* __restrict__ bd,
    float* __restrict__ out)
{
  const int tid   = threadIdx.x;
  const int t     = tid & 31;          // lane
  const int w     = tid >> 5;          // warp id = K-half owner = owned batch element
  const int bbase = blockIdx.x * 2;
  const int jc    = (t < 30) ? 2 * t : 0;     // column pair owned by this lane (matvec role)
  const int tn    = (t < HID) ? t : 0;        // unit owned by this lane (nonlin role)

  // hidden states DUPLICATED: hd[be][2k]=hd[be][2k+1]=h_k -> LDS.128 = two {h,h} pairs
  __shared__ __align__(16) float hd0[2][40];
  __shared__ __align__(16) float hd1[2][40];
  __shared__ __align__(8)  float sP[2][2][64];   // layer0 rec partials [warp][be][col]
  __shared__ __align__(8)  float sQ[2][2][64];   // layer1 acc partials
  __shared__ __align__(8)  float sR[2][2][64];   // layer1 rec partials
  __shared__ int xs[2][T_LEN];

  // ---- resident weights: this warp's K-half, packed f32x2 column pairs (60 regs) ----
  u64 u0w[10], w1w[10], u1w[10];
#pragma unroll
  for (int i = 0; i < 10; i++){
    const int row = w * 10 + i;
    u0w[i] = *(const u64*)(U0 + row * H3 + jc);
    w1w[i] = *(const u64*)(W1 + row * H3 + jc);
    u1w[i] = *(const u64*)(U1 + row * H3 + jc);
  }
  // matvec-path biases live in warp0's partial chains
  const u64 b0rp = (w == 0) ? *(const u64*)(b0r + jc) : 0ull;
  const u64 b1ip = (w == 0) ? *(const u64*)(b1i + jc) : 0ull;
  const u64 b1rp = (w == 0) ? *(const u64*)(b1r + jc) : 0ull;
  // nonlin-path input bias (scalar, own unit)
  const float b0iz = b0i[tn], b0ir = b0i[20 + tn], b0ih = b0i[40 + tn];

#pragma unroll
  for (int i = tid; i < 80; i += 64){ ((float*)hd0)[i] = 0.f; ((float*)hd1)[i] = 0.f; }
#pragma unroll 4
  for (int i = tid; i < 2 * T_LEN; i += 64) ((int*)xs)[i] = x[(long)bbase * T_LEN + i];
  __syncthreads();

  float hp0 = 0.f, hp1 = 0.f;     // lane tn of warp w keeps h_tn for batch element w

  // W0 gather for own batch element, scalar per nonlin lane, prefetched
  int row0 = xs[w][0] * H3;
  float gz = W0[row0 + tn], gr = W0[row0 + 20 + tn], gh = W0[row0 + 40 + tn];

  for (int step = 0; step < T_LEN; step++){
    const int nt   = (step + 1 < T_LEN) ? step + 1 : step;
    const int nrow = xs[w][nt] * H3;
    const float ngz = W0[nrow + tn], ngr = W0[nrow + 20 + tn], ngh = W0[nrow + 40 + tn];

    // ===== layer 0 matvec partials: this warp's K-half, both batch elements =====
#pragma unroll
    for (int be = 0; be < 2; be++){
      const ulonglong2* hv = (const ulonglong2*)hd0[be] + w * 5;
      u64 ra = b0rp, rb = 0ull;
#pragma unroll
      for (int i = 0; i < 5; i++){
        const ulonglong2 h2 = hv[i];
        ra = fma2(u0w[2*i],     h2.x, ra);
        rb = fma2(u0w[2*i + 1], h2.y, rb);
      }
      if (t < 30) *(u64*)&sP[w][be][jc] = add2(ra, rb);
    }
    __syncthreads();

    // ===== layer 0 nonlinearity: own batch element (all lanes; stores predicated) =====
    {
      const float recz = sP[0][w][tn]      + sP[1][w][tn];
      const float recr = sP[0][w][20 + tn] + sP[1][w][20 + tn];
      const float rech = sP[0][w][40 + tn] + sP[1][w][40 + tn];
      const float z  = sig_ap(gz + b0iz + recz);
      const float r  = sig_ap(gr + b0ir + recr);
      const float hh = tanh_ap(fmaf(r, rech, gh + b0ih));
      const float hn = fmaf(z, hp0 - hh, hh);
      hp0 = hn;
      if (t < HID) *(u64*)&hd0[w][2*t] = pack2(hn, hn);
    }
    __syncthreads();

    // ===== layer 1 matvec partials =====
#pragma unroll
    for (int be = 0; be < 2; be++){
      const ulonglong2* hv0 = (const ulonglong2*)hd0[be] + w * 5;
      const ulonglong2* hv1 = (const ulonglong2*)hd1[be] + w * 5;
      u64 aa = b1ip, ab = 0ull;
      u64 ra = b1rp, rb = 0ull;
#pragma unroll
      for (int i = 0; i < 5; i++){
        const ulonglong2 a2 = hv0[i];
        const ulonglong2 r2 = hv1[i];
        aa = fma2(w1w[2*i],     a2.x, aa);
        ab = fma2(w1w[2*i + 1], a2.y, ab);
        ra = fma2(u1w[2*i],     r2.x, ra);
        rb = fma2(u1w[2*i + 1], r2.y, rb);
      }
      if (t < 30){
        *(u64*)&sQ[w][be][jc] = add2(aa, ab);
        *(u64*)&sR[w][be][jc] = add2(ra, rb);
      }
    }
    __syncthreads();

    // ===== layer 1 nonlinearity: own batch element =====
    {
      const float az = sQ[0][w][tn]      + sQ[1][w][tn];
      const float ar = sQ[0][w][20 + tn] + sQ[1][w][20 + tn];
      const float ah = sQ[0][w][40 + tn] + sQ[1][w][40 + tn];
      const float rz = sR[0][w][tn]      + sR[1][w][tn];
      const float rr = sR[0][w][20 + tn] + sR[1][w][20 + tn];
      const float rh = sR[0][w][40 + tn] + sR[1][w][40 + tn];
      const float z  = sig_ap(az + rz);
      const float r  = sig_ap(ar + rr);
      const float hh = tanh_ap(fmaf(r, rh, ah));
      const float hn = fmaf(z, hp1 - hh, hh);
      hp1 = hn;
      if (t < HID) *(u64*)&hd1[w][2*t] = pack2(hn, hn);
    }
    __syncthreads();

    gz = ngz; gr = ngr; gh = ngh;
  }

  // ===== epilogue: softmax(h1 @ Wd + bd), warp w handles batch element w =====
  {
    float val = -1e30f;
    if (t < LOUT){
      float acc = bd[t];
#pragma unroll
      for (int k = 0; k < HID; k++)
        acc = fmaf(hd1[w][2*k], Wd[k * LOUT + t], acc);
      val = acc;
    }
    float m = val;
#pragma unroll
    for (int off = 16; off > 0; off >>= 1)
      m = fmaxf(m, __shfl_xor_sync(0xffffffffu, m, off));
    const float e = (t < LOUT) ? __expf(val - m) : 0.f;
    float s = e;
#pragma unroll
    for (int off = 16; off > 0; off >>= 1)
      s += __shfl_xor_sync(0xffffffffu, s, off);
    if (t < LOUT)
      out[(long)(bbase + w) * LOUT + t] = __fdividef(e, s);
  }
}

extern "C" void kernel_launch(void* const* d_in, const int* in_sizes, int n_in,
                              void* d_out, int out_size)
{
  const int*   x   = (const int*)  d_in[0];
  const float* W0  = (const float*)d_in[1];
  const float* U0  = (const float*)d_in[2];
  const float* b0i = (const float*)d_in[3];
  const float* b0r = (const float*)d_in[4];
  const float* W1  = (const float*)d_in[5];
  const float* U1  = (const float*)d_in[6];
  const float* b1i = (const float*)d_in[7];
  const float* b1r = (const float*)d_in[8];
  const float* Wd  = (const float*)d_in[9];
  const float* bd  = (const float*)d_in[10];
  // d_in[11] = drop_rate (identity, ignored)
  float* out = (float*)d_out;

  gru2_kernel<<<NB / 2, 64>>>(x, W0, U0, b0i, b0r, W1, U1, b1i, b1r, Wd, bd, out);
}

// round 10
// speedup vs baseline: 2.5857x; 1.4370x over previous
#include <cuda_runtime.h>
#include <cuda_bf16.h>

typedef unsigned long long u64;

#define T_LEN  128
#define H3     60
#define HID    20
#define LOUT   15
#define NB     2048

__device__ __forceinline__ u64 fma2(u64 a, u64 b, u64 c){
  u64 d; asm("fma.rn.f32x2 %0, %1, %2, %3;" : "=l"(d) : "l"(a), "l"(b), "l"(c)); return d;
}
__device__ __forceinline__ u64 pack2(float x, float y){
  u64 d; asm("mov.b64 %0, {%1, %2};" : "=l"(d) : "f"(x), "f"(y)); return d;
}
__device__ __forceinline__ float2 unpk(u64 v){
  float2 f; asm("mov.b64 {%0, %1}, %2;" : "=f"(f.x), "=f"(f.y) : "l"(v)); return f;
}
__device__ __forceinline__ float tanh_ap(float x){
  float y; asm("tanh.approx.f32 %0, %1;" : "=f"(y) : "f"(x)); return y;
}
__device__ __forceinline__ float sig_ap(float x){
  return fmaf(0.5f, tanh_ap(0.5f * x), 0.5f);
}

__global__ void __launch_bounds__(32) gru2_kernel(
    const int*   __restrict__ x,
    const float* __restrict__ W0,
    const float* __restrict__ U0,  const float* __restrict__ b0i, const float* __restrict__ b0r,
    const float* __restrict__ W1,  const float* __restrict__ U1,
    const float* __restrict__ b1i, const float* __restrict__ b1r,
    const float* __restrict__ Wd,  const float* __restrict__ bd,
    float* __restrict__ out)
{
  const int t     = threadIdx.x;
  const int bbase = blockIdx.x * 2;
  const int tl    = (t < 30) ? t : 0;
  // column ownership: lane u<20 owns z-col u and r-col 20+u (gate preacts lane-local);
  // lane 20+a owns xh-cols 40+2a, 41+2a (exported to nonlin lanes via shfl)
  const int c0    = (tl < 20) ? tl : 40 + 2 * (tl - 20);
  const int c1    = (tl < 20) ? 20 + tl : c0 + 1;
  const int hsrc  = 20 + (tl >> 1);      // h-lane holding xh/rh for unit tl
  const int odd   = tl & 1;

  // hidden states: plain 20-float arrays (K-packed pairs read as ulonglong2)
  __shared__ __align__(16) float hs0[2][20];
  __shared__ __align__(16) float hs1[2][20];
  __shared__ int xs[2][T_LEN];

  // ---- weights K-packed per owned column: wp[col_slot][i] = {W[2i,c],W[2i+1,c]} ----
  u64 u0p[2][10], w1p[2][10], u1p[2][10];
#pragma unroll
  for (int i = 0; i < 10; i++){
    u0p[0][i] = pack2(U0[(2*i) * H3 + c0], U0[(2*i + 1) * H3 + c0]);
    u0p[1][i] = pack2(U0[(2*i) * H3 + c1], U0[(2*i + 1) * H3 + c1]);
    w1p[0][i] = pack2(W1[(2*i) * H3 + c0], W1[(2*i + 1) * H3 + c0]);
    w1p[1][i] = pack2(W1[(2*i) * H3 + c1], W1[(2*i + 1) * H3 + c1]);
    u1p[0][i] = pack2(U1[(2*i) * H3 + c0], U1[(2*i + 1) * H3 + c0]);
    u1p[1][i] = pack2(U1[(2*i) * H3 + c1], U1[(2*i + 1) * H3 + c1]);
  }
  const float bi0_0 = b0i[c0], bi0_1 = b0i[c1];
  const float br0_0 = b0r[c0], br0_1 = b0r[c1];
  const float bi1_0 = b1i[c0], bi1_1 = b1i[c1];
  const float br1_0 = b1r[c0], br1_1 = b1r[c1];

#pragma unroll
  for (int i = t; i < 40; i += 32){ ((float*)hs0)[i] = 0.f; ((float*)hs1)[i] = 0.f; }
#pragma unroll 4
  for (int i = t; i < T_LEN; i += 32){
    xs[0][i] = x[(long)bbase * T_LEN + i];
    xs[1][i] = x[(long)(bbase + 1) * T_LEN + i];
  }
  __syncwarp();

  float hp0[2] = {0.f, 0.f};   // lane u<20 keeps h_u per layer per batch element
  float hp1[2] = {0.f, 0.f};

  // register-carried h0 K-pairs: h0c[be][i] = {h0_2i, h0_2i+1}
  u64 h0c[2][10];
#pragma unroll
  for (int be = 0; be < 2; be++)
#pragma unroll
    for (int i = 0; i < 10; i++) h0c[be][i] = 0ull;

  // W0 gather for owned columns (+ b0i), prefetched one step ahead
  float g0[2], g1[2];
#pragma unroll
  for (int be = 0; be < 2; be++){
    const int row = xs[be][0] * H3;
    g0[be] = W0[row + c0] + bi0_0;
    g1[be] = W0[row + c1] + bi0_1;
  }

  for (int step = 0; step < T_LEN; step++){
    const int nt = (step + 1 < T_LEN) ? step + 1 : step;
    float ng0[2], ng1[2];
#pragma unroll
    for (int be = 0; be < 2; be++){
      const int nrow = xs[be][nt] * H3;
      ng0[be] = W0[nrow + c0] + bi0_0;
      ng1[be] = W0[nrow + c1] + bi0_1;
    }

    // ===== layer 0: matvec on carried h0 (zero loads) + nonlinearity =====
#pragma unroll
    for (int be = 0; be < 2; be++){
      u64 a0 = 0ull, a1 = 0ull;
#pragma unroll
      for (int i = 0; i < 10; i++){
        a0 = fma2(u0p[0][i], h0c[be][i], a0);
        a1 = fma2(u0p[1][i], h0c[be][i], a1);
      }
      const float2 f0 = unpk(a0), f1 = unpk(a1);
      const float e0 = f0.x + f0.y + br0_0;     // rec preact, col c0
      const float e1 = f1.x + f1.y + br0_1;     // rec preact, col c1
      // export h-lane (xh, rh) pairs to nonlin lanes
      const u64 xq = __shfl_sync(0xffffffffu, pack2(g0[be], g1[be]), hsrc);
      const u64 rq = __shfl_sync(0xffffffffu, pack2(e0, e1),         hsrc);
      const float z = sig_ap(g0[be] + e0);      // lane-local z (col u)
      const float r = sig_ap(g1[be] + e1);      // lane-local r (col 20+u)
      const float2 xf = unpk(xq), rf = unpk(rq);
      const float xh = odd ? xf.y : xf.x;
      const float rh = odd ? rf.y : rf.x;
      const float hh = tanh_ap(fmaf(r, rh, xh));
      const float hn = fmaf(z, hp0[be] - hh, hh);
      hp0[be] = hn;
      if (t < HID) hs0[be][t] = hn;
    }
    __syncwarp();

    // ===== layer 1 matvec: fresh h0 (doubles as next-step carry) + old h1 =====
    float ga[2], gb[2], ea[2], eb[2];
#pragma unroll
    for (int be = 0; be < 2; be++){
      const ulonglong2* p0 = (const ulonglong2*)hs0[be];
      const ulonglong2* p1 = (const ulonglong2*)hs1[be];
      u64 a0 = 0ull, a1 = 0ull, r0 = 0ull, r1 = 0ull;
#pragma unroll
      for (int i = 0; i < 5; i++){
        const ulonglong2 q0 = p0[i];
        const ulonglong2 q1 = p1[i];
        h0c[be][2*i]     = q0.x;              // carry for next step's MV0
        h0c[be][2*i + 1] = q0.y;
        a0 = fma2(w1p[0][2*i], q0.x, a0);  a0 = fma2(w1p[0][2*i + 1], q0.y, a0);
        a1 = fma2(w1p[1][2*i], q0.x, a1);  a1 = fma2(w1p[1][2*i + 1], q0.y, a1);
        r0 = fma2(u1p[0][2*i], q1.x, r0);  r0 = fma2(u1p[0][2*i + 1], q1.y, r0);
        r1 = fma2(u1p[1][2*i], q1.x, r1);  r1 = fma2(u1p[1][2*i + 1], q1.y, r1);
      }
      const float2 fa0 = unpk(a0), fa1 = unpk(a1), fr0 = unpk(r0), fr1 = unpk(r1);
      ga[be] = fa0.x + fa0.y + bi1_0;           // input-path preact, col c0
      gb[be] = fa1.x + fa1.y + bi1_1;           // input-path preact, col c1
      ea[be] = fr0.x + fr0.y + br1_0;           // rec-path preact, col c0
      eb[be] = fr1.x + fr1.y + br1_1;           // rec-path preact, col c1
    }
    __syncwarp();   // all hs1 reads complete before NL1 overwrites

    // ===== layer 1 nonlinearity =====
#pragma unroll
    for (int be = 0; be < 2; be++){
      const u64 xq = __shfl_sync(0xffffffffu, pack2(ga[be], gb[be]), hsrc);
      const u64 rq = __shfl_sync(0xffffffffu, pack2(ea[be], eb[be]), hsrc);
      const float z = sig_ap(ga[be] + ea[be]);
      const float r = sig_ap(gb[be] + eb[be]);
      const float2 xf = unpk(xq), rf = unpk(rq);
      const float xh = odd ? xf.y : xf.x;
      const float rh = odd ? rf.y : rf.x;
      const float hh = tanh_ap(fmaf(r, rh, xh));
      const float hn = fmaf(z, hp1[be] - hh, hh);
      hp1[be] = hn;
      if (t < HID) hs1[be][t] = hn;
    }
    __syncwarp();   // NL1 stores visible before next step's MV1 loads

#pragma unroll
    for (int be = 0; be < 2; be++){ g0[be] = ng0[be]; g1[be] = ng1[be]; }
  }

  // ===== epilogue: softmax(h1 @ Wd + bd) =====
#pragma unroll
  for (int be = 0; be < 2; be++){
    float val = -1e30f;
    if (t < LOUT){
      float acc = bd[t];
#pragma unroll
      for (int k = 0; k < HID; k++)
        acc = fmaf(hs1[be][k], Wd[k * LOUT + t], acc);
      val = acc;
    }
    float m = val;
#pragma unroll
    for (int off = 16; off > 0; off >>= 1)
      m = fmaxf(m, __shfl_xor_sync(0xffffffffu, m, off));
    const float e = (t < LOUT) ? __expf(val - m) : 0.f;
    float s = e;
#pragma unroll
    for (int off = 16; off > 0; off >>= 1)
      s += __shfl_xor_sync(0xffffffffu, s, off);
    if (t < LOUT)
      out[(long)(bbase + be) * LOUT + t] = __fdividef(e, s);
  }
}

extern "C" void kernel_launch(void* const* d_in, const int* in_sizes, int n_in,
                              void* d_out, int out_size)
{
  const int*   x   = (const int*)  d_in[0];
  const float* W0  = (const float*)d_in[1];
  const float* U0  = (const float*)d_in[2];
  const float* b0i = (const float*)d_in[3];
  const float* b0r = (const float*)d_in[4];
  const float* W1  = (const float*)d_in[5];
  const float* U1  = (const float*)d_in[6];
  const float* b1i = (const float*)d_in[7];
  const float* b1r = (const float*)d_in[8];
  const float* Wd  = (const float*)d_in[9];
  const float* bd  = (const float*)d_in[10];
  // d_in[11] = drop_rate (identity, ignored)
  float* out = (float*)d_out;

  gru2_kernel<<<NB / 2, 32>>>(x, W0, U0, b0i, b0r, W1, U1, b1i, b1r, Wd, bd, out);
}